// round 9
// baseline (speedup 1.0000x reference)
#include <cuda_runtime.h>

#define CC   10
#define HH   30
#define WW   30
#define DD   11
#define FULL 0xFFFFFFFFu

__device__ __forceinline__ float rsum16(float v) {
    #pragma unroll
    for (int o = 1; o < 16; o <<= 1) v += __shfl_xor_sync(FULL, v, o);
    return v;
}

__global__ __launch_bounds__(64) void pve_kernel(
    const float* __restrict__ x,      // [2,10,30,30] one-hot
    const float* __restrict__ w_in,   // [33,11]
    const float* __restrict__ w_out,  // [11,11]
    const float* __restrict__ w_ff1,  // [1,11]
    const float* __restrict__ w_ff2,  // [11,1]
    const float* __restrict__ ln1_g,  // [11]
    const float* __restrict__ ln2_g,  // [11]
    float* __restrict__ out)          // [1800,10,100]
{
    __shared__ union { unsigned char b[100]; unsigned int w[25]; } wtab;
    __shared__ float pvs[10];

    const int tid  = threadIdx.x;     // 0..63
    const int lane = tid & 31;
    const int wrp  = tid >> 5;        // 0 or 1
    const int b    = blockIdx.x;      // pixel id 0..1799
    const int n    = b / 900;
    const int rem  = b % 900;
    const int pi   = rem / 30, pj = rem % 30;

    const bool haspad = (pi < 4) | (pi > HH - 5) | (pj < 4) | (pj > WW - 5);

    // ── warp 0: hoist weight loads to overlap decode (border only) ──
    const int d = lane;
    float kk[DD], vv[DD], wo[DD];
    float q10 = 0.f, g1 = 0.f, g2 = 0.f, f1 = 0.f, f2 = 0.f;
    if (haspad && wrp == 0 && d < DD) {
        q10 = w_in[d * DD + 10];
        g1  = ln1_g[d];
        g2  = ln2_g[d];
        f1  = w_ff1[d];
        f2  = w_ff2[d];
        #pragma unroll
        for (int c = 0; c < DD; c++) {
            kk[c] = w_in[(DD + d) * DD + c];
            vv[c] = w_in[(2 * DD + d) * DD + c];
            wo[c] = w_out[d * DD + c];
        }
    }

    // ── decode: thread handles slots tid and tid+64 (byte-granular STS) ──
    const float* xn = x + (long)n * (CC * HH * WW);
    #pragma unroll
    for (int pass = 0; pass < 2; pass++) {
        int s = tid + pass * 64;
        if (s < 100) {
            int mh = s / 10, mw = s % 10;
            unsigned int cls = 255;
            if (mh < 9 && mw < 9) {
                int si = pi + mh - 4, sj = pj + mw - 4;
                cls = 10;
                if (si >= 0 && si < HH && sj >= 0 && sj < WW) {
                    const float* px = xn + si * WW + sj;
                    float acc = 0.f;
                    #pragma unroll
                    for (int c = 1; c < CC; c++) acc += (float)c * px[c * HH * WW];
                    cls = __float2int_rn(acc);
                }
            }
            wtab.b[s] = (unsigned char)cls;
        }
    }
    __syncthreads();

    // ── border pipeline on warp 0 only ──
    if (haspad && wrp == 0) {
        unsigned int word = (lane < 25) ? wtab.w[lane] : 0xFFFFFFFFu;

        // fused histogram (vcmp+popc+redux) + attention for query class 10
        float num = 0.f, den = 0.f;
        #pragma unroll
        for (int c = 0; c < DD; c++) {
            unsigned int eq  = __vcmpeq4(word, c * 0x01010101u);
            int          cnt = __popc(eq) >> 3;
            int          hc  = __reduce_add_sync(FULL, cnt);
            if (d < DD) {
                float e = __expf(q10 * kk[c]) * (float)hc;
                den += e;
                num += e * vv[c];
            }
        }
        float ao = (d < DD) ? num / den : 0.f;

        // svec = e_10 + ao @ w_out^T
        float acc = (d == 10) ? 1.f : 0.f;
        #pragma unroll
        for (int c = 0; c < DD; c++) {
            float a = __shfl_sync(FULL, ao, c);
            if (d < DD) acc += a * wo[c];
        }
        float sv = (d < DD) ? acc : 0.f;

        // LN1 (mean & E[x^2], independent reduction chains)
        float s1 = rsum16(sv);
        float s2 = rsum16(sv * sv);
        float m   = s1 * (1.f / 11.f);
        float var = fmaxf(s2 * (1.f / 11.f) - m * m, 0.f);
        float inv = rsqrtf(var + 1e-5f);
        float h1  = (d < DD) ? (sv - m) * inv * g1 : 0.f;

        // FF
        float tt = rsum16(h1 * f1);
        tt = fmaxf(tt, 0.f);
        float h2 = (d < DD) ? h1 + tt * f2 : 0.f;

        // LN2
        float t1 = rsum16(h2);
        float t2 = rsum16(h2 * h2);
        float m2   = t1 * (1.f / 11.f);
        float var2 = fmaxf(t2 * (1.f / 11.f) - m2 * m2, 0.f);
        float inv2 = rsqrtf(var2 + 1e-5f);
        float hhv  = (d < DD) ? (h2 - m2) * inv2 * g2 : 0.f;

        // softmax over classes 0..9 (post-LN values bounded: no max-sub)
        float ex = (d < CC) ? __expf(hhv) : 0.f;
        float se = rsum16(ex);
        if (d < CC) pvs[d] = ex / se;
    }
    if (haspad) __syncthreads();   // uniform per block: legal

    // ── scatter 250 float4 across both warps (q = c*25 + j) ──
    float4* o4 = reinterpret_cast<float4*>(out + (long)b * 1000);
    #pragma unroll
    for (int it = 0; it < 4; it++) {
        int q = tid + it * 64;
        if (q < 250) {
            int c = q / 25;
            int j = q - c * 25;
            unsigned int wd = wtab.w[j];
            float        pc = haspad ? pvs[c] : 0.f;
            float4 r;
            float* rp = &r.x;
            #pragma unroll
            for (int e = 0; e < 4; e++) {
                unsigned int cls = (wd >> (8 * e)) & 0xFF;
                rp[e] = (cls == 10u) ? pc : ((cls == (unsigned)c) ? 1.0f : 0.0f);
            }
            o4[q] = r;
        }
    }
}

extern "C" void kernel_launch(void* const* d_in, const int* in_sizes, int n_in,
                              void* d_out, int out_size) {
    const float* x     = (const float*)d_in[0];
    const float* w_in  = (const float*)d_in[1];
    const float* w_out = (const float*)d_in[2];
    const float* w_ff1 = (const float*)d_in[3];
    const float* w_ff2 = (const float*)d_in[4];
    const float* ln1_g = (const float*)d_in[5];
    const float* ln2_g = (const float*)d_in[6];

    pve_kernel<<<1800, 64>>>(x, w_in, w_out, w_ff1, w_ff2, ln1_g, ln2_g,
                             (float*)d_out);
}